// round 4
// baseline (speedup 1.0000x reference)
#include <cuda_runtime.h>
#include <cstdint>

#define MAXN 100000
#define MAXE 3200000
#define INF  256
#define OUTF 64
#define ALPHA 0.2f

// Static scratch
__device__ float g_h[(size_t)MAXN * OUTF];   // 25.6 MB
__device__ float g_s1[MAXN];
__device__ float g_s2[MAXN];
__device__ float g_den[MAXN];
__device__ int   g_deg[MAXN];                // degree by src
__device__ int   g_ptr[MAXN];                // CSR row starts
__device__ int   g_cur[MAXN];                // scatter cursors
__device__ int   g_bsum[128];                // scan partials
__device__ int2  g_pack[MAXE];               // (dst, exp(e)) grouped by src
__device__ float g_wt[INF * OUTF];           // W transposed [k][o]
__device__ int   g_is64;

// ---------------------------------------------------------------------------
__global__ void k_detect(const int* __restrict__ adj32, int E) {
    __shared__ int sh[256];
    int t = threadIdx.x;
    int acc = 0;
#pragma unroll
    for (int j = 0; j < 4; j++) {
        int idx = 2 * (t * 4 + j) + 1;
        if (idx < 2 * E) acc |= adj32[idx];
    }
    sh[t] = acc;
    __syncthreads();
    for (int s = 128; s; s >>= 1) {
        if (t < s) sh[t] |= sh[t + s];
        __syncthreads();
    }
    if (t == 0) g_is64 = (sh[0] == 0) ? 1 : 0;
}

__global__ void k_wt(const float* __restrict__ W) {
    int i = blockIdx.x * blockDim.x + threadIdx.x;
    if (i < INF * OUTF) {
        int k = i >> 6, o = i & 63;
        g_wt[i] = W[o * INF + k];
    }
}

__global__ void k_init(int N) {
    int i = blockIdx.x * blockDim.x + threadIdx.x;
    if (i < N) { g_den[i] = 0.0f; g_deg[i] = 0; }
}

// Degree histogram over src
__global__ void k_degree(const void* __restrict__ adj, int E) {
    int i = blockIdx.x * blockDim.x + threadIdx.x;
    if (i >= E) return;
    int s = g_is64 ? (int)((const long long*)adj)[i] : ((const int*)adj)[i];
    atomicAdd(&g_deg[s], 1);
}

// ---------------------------------------------------------------------------
// SGEMM: h = x @ W^T + b, fused s1/s2. Tile M=256 x N=64, micro 8x8.
// 256 threads: tx = t&7 (n0=tx*8), ty = t>>3 (m0=ty*8).
// ---------------------------------------------------------------------------
#define XS_STRIDE 260
__global__ void __launch_bounds__(256) k_gemm(
    const float* __restrict__ x, const float* __restrict__ b,
    const float* __restrict__ a, int N)
{
    __shared__ float Ws[128 * 64];              // 32 KB: half of Wt
    __shared__ float xs[2][16 * XS_STRIDE];     // 2 x 16.6 KB

    int t  = threadIdx.x;
    int tx = t & 7;
    int ty = t >> 3;
    int base = blockIdx.x * 256;

    float acc[8][8];
#pragma unroll
    for (int i = 0; i < 8; i++)
#pragma unroll
        for (int j = 0; j < 8; j++) acc[i][j] = 0.f;

#pragma unroll
    for (int half = 0; half < 2; half++) {
        // Stage this half of Wt (128 k x 64 o)
        {
            const float4* wp = (const float4*)(g_wt + half * 128 * 64);
            float4* wsp = (float4*)Ws;
#pragma unroll
            for (int i = 0; i < 8; i++) wsp[t + 256 * i] = __ldg(wp + t + 256 * i);
        }
        // Preload first x chunk (16 k x 256 m) into xs[0]
#pragma unroll
        for (int r = 0; r < 4; r++) {
            int idx = t + 256 * r;
            int row = idx >> 2, q = idx & 3;
            int node = base + row;
            float4 v = make_float4(0.f, 0.f, 0.f, 0.f);
            if (node < N) v = __ldg((const float4*)(x + (size_t)node * INF) + half * 32 + q);
            float* dst = xs[0];
            dst[(q * 4 + 0) * XS_STRIDE + row] = v.x;
            dst[(q * 4 + 1) * XS_STRIDE + row] = v.y;
            dst[(q * 4 + 2) * XS_STRIDE + row] = v.z;
            dst[(q * 4 + 3) * XS_STRIDE + row] = v.w;
        }
        __syncthreads();

#pragma unroll
        for (int kc = 0; kc < 8; kc++) {
            int buf = kc & 1;
            if (kc < 7) {   // prefetch next chunk into other buffer
#pragma unroll
                for (int r = 0; r < 4; r++) {
                    int idx = t + 256 * r;
                    int row = idx >> 2, q = idx & 3;
                    int node = base + row;
                    float4 v = make_float4(0.f, 0.f, 0.f, 0.f);
                    if (node < N)
                        v = __ldg((const float4*)(x + (size_t)node * INF) + half * 32 + (kc + 1) * 4 + q);
                    float* dst = xs[buf ^ 1];
                    dst[(q * 4 + 0) * XS_STRIDE + row] = v.x;
                    dst[(q * 4 + 1) * XS_STRIDE + row] = v.y;
                    dst[(q * 4 + 2) * XS_STRIDE + row] = v.z;
                    dst[(q * 4 + 3) * XS_STRIDE + row] = v.w;
                }
            }
#pragma unroll
            for (int kk = 0; kk < 16; kk++) {
                float4 b0 = *(const float4*)&Ws[(kc * 16 + kk) * 64 + tx * 8];
                float4 b1 = *(const float4*)&Ws[(kc * 16 + kk) * 64 + tx * 8 + 4];
                float4 a0 = *(const float4*)&xs[buf][kk * XS_STRIDE + ty * 8];
                float4 a1 = *(const float4*)&xs[buf][kk * XS_STRIDE + ty * 8 + 4];
                float am[8] = {a0.x, a0.y, a0.z, a0.w, a1.x, a1.y, a1.z, a1.w};
                float bn[8] = {b0.x, b0.y, b0.z, b0.w, b1.x, b1.y, b1.z, b1.w};
#pragma unroll
                for (int mi = 0; mi < 8; mi++)
#pragma unroll
                    for (int ni = 0; ni < 8; ni++)
                        acc[mi][ni] += am[mi] * bn[ni];
            }
            __syncthreads();
        }
    }

    // Epilogue
    float4 bb0  = __ldg((const float4*)b + 2 * tx);
    float4 bb1  = __ldg((const float4*)b + 2 * tx + 1);
    float4 a10  = __ldg((const float4*)a + 2 * tx);
    float4 a11  = __ldg((const float4*)a + 2 * tx + 1);
    float4 a20  = __ldg((const float4*)(a + OUTF) + 2 * tx);
    float4 a21  = __ldg((const float4*)(a + OUTF) + 2 * tx + 1);

#pragma unroll
    for (int mi = 0; mi < 8; mi++) {
        int node = base + ty * 8 + mi;
        float4 h0, h1;
        h0.x = acc[mi][0] + bb0.x; h0.y = acc[mi][1] + bb0.y;
        h0.z = acc[mi][2] + bb0.z; h0.w = acc[mi][3] + bb0.w;
        h1.x = acc[mi][4] + bb1.x; h1.y = acc[mi][5] + bb1.y;
        h1.z = acc[mi][6] + bb1.z; h1.w = acc[mi][7] + bb1.w;
        if (node < N) {
            float4* hp = (float4*)(g_h + (size_t)node * OUTF);
            hp[2 * tx]     = h0;
            hp[2 * tx + 1] = h1;
        }
        float p1 = h0.x * a10.x + h0.y * a10.y + h0.z * a10.z + h0.w * a10.w
                 + h1.x * a11.x + h1.y * a11.y + h1.z * a11.z + h1.w * a11.w;
        float p2 = h0.x * a20.x + h0.y * a20.y + h0.z * a20.z + h0.w * a20.w
                 + h1.x * a21.x + h1.y * a21.y + h1.z * a21.z + h1.w * a21.w;
#pragma unroll
        for (int off = 4; off; off >>= 1) {
            p1 += __shfl_xor_sync(0xffffffffu, p1, off);
            p2 += __shfl_xor_sync(0xffffffffu, p2, off);
        }
        if (tx == 0 && node < N) {
            g_s1[node] = p1;
            g_s2[node] = p2;
        }
    }
}

// ---------------------------------------------------------------------------
// Exclusive scan of g_deg -> g_ptr
// ---------------------------------------------------------------------------
__global__ void k_scanA(int N) {
    __shared__ int sh[1024];
    int i = blockIdx.x * 1024 + threadIdx.x;
    int v = (i < N) ? g_deg[i] : 0;
    sh[threadIdx.x] = v;
    __syncthreads();
#pragma unroll
    for (int off = 1; off < 1024; off <<= 1) {
        int add = (threadIdx.x >= off) ? sh[threadIdx.x - off] : 0;
        __syncthreads();
        sh[threadIdx.x] += add;
        __syncthreads();
    }
    if (i < N) g_ptr[i] = sh[threadIdx.x] - v;
    if (threadIdx.x == 1023) g_bsum[blockIdx.x] = sh[1023];
}

__global__ void k_scanB(int nb) {
    if (threadIdx.x == 0) {
        int acc = 0;
        for (int b = 0; b < nb; b++) { int t = g_bsum[b]; g_bsum[b] = acc; acc += t; }
    }
}

__global__ void k_scanC(int N) {
    int i = blockIdx.x * blockDim.x + threadIdx.x;
    if (i < N) {
        int p = g_ptr[i] + g_bsum[i >> 10];
        g_ptr[i] = p;
        g_cur[i] = p;
    }
}

// ---------------------------------------------------------------------------
// Fused: ex = exp(leakyrelu(s1[src]+s2[dst])), denom atomic, CSR scatter.
// ---------------------------------------------------------------------------
__global__ void k_edge12(const void* __restrict__ adj, int E) {
    int i = blockIdx.x * blockDim.x + threadIdx.x;
    if (i >= E) return;
    int s, d;
    if (g_is64) {
        const long long* a = (const long long*)adj;
        s = (int)a[i];
        d = (int)a[(size_t)i + E];
    } else {
        const int* a = (const int*)adj;
        s = a[i];
        d = a[(size_t)i + E];
    }
    float e = g_s1[s] + g_s2[d];
    e = e > 0.f ? e : ALPHA * e;
    float ex = __expf(e);
    atomicAdd(&g_den[d], ex);
    int pos = atomicAdd(&g_cur[s], 1);
    g_pack[pos] = make_int2(d, __float_as_int(ex));
}

// ---------------------------------------------------------------------------
// CSR aggregation: out[n] = elu( sum_j (ex_j/den[d_j]) * h[d_j] ), 16 lanes/node
// ---------------------------------------------------------------------------
__global__ void __launch_bounds__(256) k_edge3(float* __restrict__ out, int N) {
    int t = threadIdx.x;
    int node = blockIdx.x * 16 + (t >> 4);
    int lane = t & 15;
    if (node >= N) return;
    int start = g_ptr[node];
    int deg   = g_deg[node];
    float4 acc = make_float4(0.f, 0.f, 0.f, 0.f);
    if (deg > 0) {
        int2 p = __ldg(&g_pack[start]);
        for (int j = 0; j < deg - 1; j++) {
            int2 pn = __ldg(&g_pack[start + j + 1]);
            int d = p.x;
            float att = __fdividef(__int_as_float(p.y), __ldg(&g_den[d]));
            float4 hv = __ldg((const float4*)(g_h + (size_t)d * OUTF) + lane);
            acc.x += att * hv.x; acc.y += att * hv.y;
            acc.z += att * hv.z; acc.w += att * hv.w;
            p = pn;
        }
        int d = p.x;
        float att = __fdividef(__int_as_float(p.y), __ldg(&g_den[d]));
        float4 hv = __ldg((const float4*)(g_h + (size_t)d * OUTF) + lane);
        acc.x += att * hv.x; acc.y += att * hv.y;
        acc.z += att * hv.z; acc.w += att * hv.w;
    }
    acc.x = acc.x > 0.f ? acc.x : expm1f(acc.x);
    acc.y = acc.y > 0.f ? acc.y : expm1f(acc.y);
    acc.z = acc.z > 0.f ? acc.z : expm1f(acc.z);
    acc.w = acc.w > 0.f ? acc.w : expm1f(acc.w);
    *((float4*)(out + (size_t)node * OUTF) + lane) = acc;
}

extern "C" void kernel_launch(void* const* d_in, const int* in_sizes, int n_in,
                              void* d_out, int out_size)
{
    const void*  adj = d_in[0];
    const float* x   = (const float*)d_in[1];
    const float* W   = (const float*)d_in[2];
    const float* b   = (const float*)d_in[3];
    const float* a   = (const float*)d_in[4];
    float* out = (float*)d_out;

    int E = in_sizes[0] / 2;
    int N = in_sizes[1] / INF;
    int nScanBlocks = (N + 1023) / 1024;

    k_detect<<<1, 256>>>((const int*)adj, E);
    k_wt<<<(INF * OUTF + 255) / 256, 256>>>(W);
    k_init<<<(N + 255) / 256, 256>>>(N);
    k_degree<<<(E + 255) / 256, 256>>>(adj, E);
    k_gemm<<<(N + 255) / 256, 256>>>(x, b, a, N);
    k_scanA<<<nScanBlocks, 1024>>>(N);
    k_scanB<<<1, 32>>>(nScanBlocks);
    k_scanC<<<(N + 255) / 256, 256>>>(N);
    k_edge12<<<(E + 255) / 256, 256>>>(adj, E);
    k_edge3<<<(N + 15) / 16, 256>>>(out, N);
}

// round 5
// speedup vs baseline: 1.2259x; 1.2259x over previous
#include <cuda_runtime.h>
#include <cstdint>

#define MAXN 100000
#define MAXE 3200000
#define INF  256
#define OUTF 64
#define ALPHA 0.2f

// Static scratch
__device__ float g_h[(size_t)MAXN * OUTF];   // 25.6 MB
__device__ float g_s1[MAXN];
__device__ float g_s2[MAXN];
__device__ float g_den[MAXN];
__device__ int   g_src[MAXE];                // int32 src
__device__ int   g_dst[MAXE];                // int32 dst
__device__ int   g_deg[MAXN];                // degree by src
__device__ int   g_ptr[MAXN];                // CSR row starts
__device__ int   g_cur[MAXN];                // scatter cursors
__device__ int   g_bsum[128];                // scan partials
__device__ int2  g_pack[MAXE];               // (dst, exp(e)) grouped by src
__device__ float g_wt[INF * OUTF];           // W transposed [k][o]
__device__ int   g_is64;

// ---------------------------------------------------------------------------
__global__ void k_detect(const int* __restrict__ adj32, int E) {
    __shared__ int sh[256];
    int t = threadIdx.x;
    int acc = 0;
#pragma unroll
    for (int j = 0; j < 4; j++) {
        int idx = 2 * (t * 4 + j) + 1;
        if (idx < 2 * E) acc |= adj32[idx];
    }
    sh[t] = acc;
    __syncthreads();
    for (int s = 128; s; s >>= 1) {
        if (t < s) sh[t] |= sh[t + s];
        __syncthreads();
    }
    if (t == 0) g_is64 = (sh[0] == 0) ? 1 : 0;
}

__global__ void k_wt(const float* __restrict__ W) {
    int i = blockIdx.x * blockDim.x + threadIdx.x;
    if (i < INF * OUTF) {
        int k = i >> 6, o = i & 63;
        g_wt[i] = W[o * INF + k];
    }
}

__global__ void k_init(int N) {
    int i = blockIdx.x * blockDim.x + threadIdx.x;
    if (i < N) { g_den[i] = 0.0f; g_deg[i] = 0; }
}

// ---------------------------------------------------------------------------
// SGEMM (measured-best config): tile M=64 x N=64, 16x16 threads, 4x4 micro.
// ---------------------------------------------------------------------------
#define XS_STRIDE 68
__global__ void __launch_bounds__(256) k_gemm(
    const float* __restrict__ x, const float* __restrict__ b,
    const float* __restrict__ a, int N)
{
    __shared__ float Ws[128 * 64];              // 32 KB: half of Wt
    __shared__ float xs[2][16 * XS_STRIDE];

    int t  = threadIdx.x;
    int tx = t & 15;
    int ty = t >> 4;
    int base = blockIdx.x * 64;

    int m_l = t >> 2, q_l = t & 3;

    float4 acc[4];
#pragma unroll
    for (int i = 0; i < 4; i++) acc[i] = make_float4(0.f, 0.f, 0.f, 0.f);

    const float4* xrow = (const float4*)(x + (size_t)(base + m_l) * INF);
    bool mvalid = (base + m_l) < N;

#pragma unroll
    for (int half = 0; half < 2; half++) {
        {
            const float4* wp = (const float4*)(g_wt + half * 128 * 64);
            float4* wsp = (float4*)Ws;
#pragma unroll
            for (int i = 0; i < 8; i++) wsp[t + 256 * i] = __ldg(wp + t + 256 * i);
        }
        {
            float4 v = make_float4(0.f, 0.f, 0.f, 0.f);
            if (mvalid) v = __ldg(xrow + (half * 8) * 4 + q_l);
            float* dst = xs[0];
            dst[(q_l * 4 + 0) * XS_STRIDE + m_l] = v.x;
            dst[(q_l * 4 + 1) * XS_STRIDE + m_l] = v.y;
            dst[(q_l * 4 + 2) * XS_STRIDE + m_l] = v.z;
            dst[(q_l * 4 + 3) * XS_STRIDE + m_l] = v.w;
        }
        __syncthreads();

#pragma unroll
        for (int kc = 0; kc < 8; kc++) {
            int buf = kc & 1;
            if (kc < 7) {
                float4 v = make_float4(0.f, 0.f, 0.f, 0.f);
                if (mvalid) v = __ldg(xrow + (half * 8 + kc + 1) * 4 + q_l);
                float* dst = xs[buf ^ 1];
                dst[(q_l * 4 + 0) * XS_STRIDE + m_l] = v.x;
                dst[(q_l * 4 + 1) * XS_STRIDE + m_l] = v.y;
                dst[(q_l * 4 + 2) * XS_STRIDE + m_l] = v.z;
                dst[(q_l * 4 + 3) * XS_STRIDE + m_l] = v.w;
            }
#pragma unroll
            for (int kk = 0; kk < 16; kk++) {
                float4 bv = *(const float4*)&Ws[(kc * 16 + kk) * 64 + tx * 4];
                float4 av = *(const float4*)&xs[buf][kk * XS_STRIDE + ty * 4];
                acc[0].x += av.x * bv.x; acc[0].y += av.x * bv.y;
                acc[0].z += av.x * bv.z; acc[0].w += av.x * bv.w;
                acc[1].x += av.y * bv.x; acc[1].y += av.y * bv.y;
                acc[1].z += av.y * bv.z; acc[1].w += av.y * bv.w;
                acc[2].x += av.z * bv.x; acc[2].y += av.z * bv.y;
                acc[2].z += av.z * bv.z; acc[2].w += av.z * bv.w;
                acc[3].x += av.w * bv.x; acc[3].y += av.w * bv.y;
                acc[3].z += av.w * bv.z; acc[3].w += av.w * bv.w;
            }
            __syncthreads();
        }
    }

    float4 b4  = __ldg((const float4*)b + tx);
    float4 a1v = __ldg((const float4*)a + tx);
    float4 a2v = __ldg((const float4*)(a + OUTF) + tx);

#pragma unroll
    for (int mi = 0; mi < 4; mi++) {
        int node = base + ty * 4 + mi;
        float4 h;
        h.x = acc[mi].x + b4.x; h.y = acc[mi].y + b4.y;
        h.z = acc[mi].z + b4.z; h.w = acc[mi].w + b4.w;
        if (node < N)
            *((float4*)(g_h + (size_t)node * OUTF) + tx) = h;
        float p1 = h.x * a1v.x + h.y * a1v.y + h.z * a1v.z + h.w * a1v.w;
        float p2 = h.x * a2v.x + h.y * a2v.y + h.z * a2v.z + h.w * a2v.w;
#pragma unroll
        for (int off = 8; off; off >>= 1) {
            p1 += __shfl_xor_sync(0xffffffffu, p1, off);
            p2 += __shfl_xor_sync(0xffffffffu, p2, off);
        }
        if (tx == 0 && node < N) {
            g_s1[node] = p1;
            g_s2[node] = p2;
        }
    }
}

// ---------------------------------------------------------------------------
// Single adj pass: convert to int32 + degree histogram by src
// ---------------------------------------------------------------------------
__global__ void k_convdeg(const void* __restrict__ adj, int E) {
    int i = blockIdx.x * blockDim.x + threadIdx.x;
    if (i >= E) return;
    int s, d;
    if (g_is64) {
        const long long* a = (const long long*)adj;
        s = (int)a[i];
        d = (int)a[(size_t)i + E];
    } else {
        const int* a = (const int*)adj;
        s = a[i];
        d = a[(size_t)i + E];
    }
    g_src[i] = s;
    g_dst[i] = d;
    atomicAdd(&g_deg[s], 1);
}

// ---------------------------------------------------------------------------
// Exclusive scan of g_deg -> g_ptr
// ---------------------------------------------------------------------------
__global__ void k_scanA(int N) {
    __shared__ int sh[1024];
    int i = blockIdx.x * 1024 + threadIdx.x;
    int v = (i < N) ? g_deg[i] : 0;
    sh[threadIdx.x] = v;
    __syncthreads();
#pragma unroll
    for (int off = 1; off < 1024; off <<= 1) {
        int add = (threadIdx.x >= off) ? sh[threadIdx.x - off] : 0;
        __syncthreads();
        sh[threadIdx.x] += add;
        __syncthreads();
    }
    if (i < N) g_ptr[i] = sh[threadIdx.x] - v;
    if (threadIdx.x == 1023) g_bsum[blockIdx.x] = sh[1023];
}

__global__ void k_scanB(int nb) {
    __shared__ int sh[128];
    int t = threadIdx.x;
    int v = (t < nb) ? g_bsum[t] : 0;
    sh[t] = v;
    __syncthreads();
#pragma unroll
    for (int off = 1; off < 128; off <<= 1) {
        int add = (t >= off) ? sh[t - off] : 0;
        __syncthreads();
        sh[t] += add;
        __syncthreads();
    }
    if (t < nb) g_bsum[t] = sh[t] - v;   // exclusive
}

__global__ void k_scanC(int N) {
    int i = blockIdx.x * blockDim.x + threadIdx.x;
    if (i < N) {
        int p = g_ptr[i] + g_bsum[i >> 10];
        g_ptr[i] = p;
        g_cur[i] = p;
    }
}

// ---------------------------------------------------------------------------
// Fused: ex = exp(leakyrelu(s1[src]+s2[dst])), denom atomic, CSR scatter.
// ---------------------------------------------------------------------------
__global__ void k_edge12(int E) {
    int i = blockIdx.x * blockDim.x + threadIdx.x;
    if (i >= E) return;
    int s = g_src[i];
    int d = g_dst[i];
    float e = g_s1[s] + g_s2[d];
    e = e > 0.f ? e : ALPHA * e;
    float ex = __expf(e);
    atomicAdd(&g_den[d], ex);
    int pos = atomicAdd(&g_cur[s], 1);
    g_pack[pos] = make_int2(d, __float_as_int(ex));
}

// ---------------------------------------------------------------------------
// CSR aggregation: out[n] = elu( sum_j (ex_j/den[d_j]) * h[d_j] ), 16 lanes/node
// ---------------------------------------------------------------------------
__global__ void __launch_bounds__(256) k_edge3(float* __restrict__ out, int N) {
    int t = threadIdx.x;
    int node = blockIdx.x * 16 + (t >> 4);
    int lane = t & 15;
    if (node >= N) return;
    int start = g_ptr[node];
    int deg   = g_deg[node];
    float4 acc = make_float4(0.f, 0.f, 0.f, 0.f);
    if (deg > 0) {
        int2 p = __ldg(&g_pack[start]);
        for (int j = 0; j < deg - 1; j++) {
            int2 pn = __ldg(&g_pack[start + j + 1]);
            int d = p.x;
            float att = __fdividef(__int_as_float(p.y), __ldg(&g_den[d]));
            float4 hv = __ldg((const float4*)(g_h + (size_t)d * OUTF) + lane);
            acc.x += att * hv.x; acc.y += att * hv.y;
            acc.z += att * hv.z; acc.w += att * hv.w;
            p = pn;
        }
        int d = p.x;
        float att = __fdividef(__int_as_float(p.y), __ldg(&g_den[d]));
        float4 hv = __ldg((const float4*)(g_h + (size_t)d * OUTF) + lane);
        acc.x += att * hv.x; acc.y += att * hv.y;
        acc.z += att * hv.z; acc.w += att * hv.w;
    }
    acc.x = acc.x > 0.f ? acc.x : expm1f(acc.x);
    acc.y = acc.y > 0.f ? acc.y : expm1f(acc.y);
    acc.z = acc.z > 0.f ? acc.z : expm1f(acc.z);
    acc.w = acc.w > 0.f ? acc.w : expm1f(acc.w);
    *((float4*)(out + (size_t)node * OUTF) + lane) = acc;
}

extern "C" void kernel_launch(void* const* d_in, const int* in_sizes, int n_in,
                              void* d_out, int out_size)
{
    const void*  adj = d_in[0];
    const float* x   = (const float*)d_in[1];
    const float* W   = (const float*)d_in[2];
    const float* b   = (const float*)d_in[3];
    const float* a   = (const float*)d_in[4];
    float* out = (float*)d_out;

    int E = in_sizes[0] / 2;
    int N = in_sizes[1] / INF;
    int nScanBlocks = (N + 1023) / 1024;

    k_detect<<<1, 256>>>((const int*)adj, E);
    k_wt<<<(INF * OUTF + 255) / 256, 256>>>(W);
    k_init<<<(N + 255) / 256, 256>>>(N);
    k_gemm<<<(N + 63) / 64, 256>>>(x, b, a, N);   // slot 4: profiled
    k_convdeg<<<(E + 255) / 256, 256>>>(adj, E);
    k_scanA<<<nScanBlocks, 1024>>>(N);
    k_scanB<<<1, 128>>>(nScanBlocks);
    k_scanC<<<(N + 255) / 256, 256>>>(N);
    k_edge12<<<(E + 255) / 256, 256>>>(E);
    k_edge3<<<(N + 15) / 16, 256>>>(out, N);
}

// round 6
// speedup vs baseline: 1.2584x; 1.0265x over previous
#include <cuda_runtime.h>
#include <cuda_fp16.h>
#include <cstdint>

#define MAXN 100000
#define MAXE 3200000
#define INF  256
#define OUTF 64
#define ALPHA 0.2f

// Static scratch
__device__ float  g_h[(size_t)MAXN * OUTF];   // 25.6 MB (fp32 h, exact softmax path)
__device__ __half g_hh[(size_t)MAXN * OUTF];  // 12.8 MB (fp16 h for gather)
__device__ float  g_s1[MAXN];
__device__ float  g_s2[MAXN];
__device__ float  g_den[MAXN];
__device__ int    g_src[MAXE];
__device__ int    g_dst[MAXE];
__device__ int    g_deg[MAXN];
__device__ int    g_ptr[MAXN];
__device__ int    g_cur[MAXN];
__device__ int    g_bsum[128];
__device__ int2   g_pack[MAXE];               // (dst, exp(e)) grouped by src
__device__ float  g_wt[INF * OUTF];
__device__ int    g_is64;

// ---------------------------------------------------------------------------
__global__ void k_detect(const int* __restrict__ adj32, int E) {
    __shared__ int sh[256];
    int t = threadIdx.x;
    int acc = 0;
#pragma unroll
    for (int j = 0; j < 4; j++) {
        int idx = 2 * (t * 4 + j) + 1;
        if (idx < 2 * E) acc |= adj32[idx];
    }
    sh[t] = acc;
    __syncthreads();
    for (int s = 128; s; s >>= 1) {
        if (t < s) sh[t] |= sh[t + s];
        __syncthreads();
    }
    if (t == 0) g_is64 = (sh[0] == 0) ? 1 : 0;
}

__global__ void k_wt(const float* __restrict__ W) {
    int i = blockIdx.x * blockDim.x + threadIdx.x;
    if (i < INF * OUTF) {
        int k = i >> 6, o = i & 63;
        g_wt[i] = W[o * INF + k];
    }
}

__global__ void k_init(int N) {
    int i = blockIdx.x * blockDim.x + threadIdx.x;
    if (i < N) { g_den[i] = 0.0f; g_deg[i] = 0; }
}

// ---------------------------------------------------------------------------
// SGEMM (measured-best config): tile M=64 x N=64, 16x16 threads, 4x4 micro.
// ---------------------------------------------------------------------------
#define XS_STRIDE 68
__global__ void __launch_bounds__(256) k_gemm(
    const float* __restrict__ x, const float* __restrict__ b,
    const float* __restrict__ a, int N)
{
    __shared__ float Ws[128 * 64];              // 32 KB: half of Wt
    __shared__ float xs[2][16 * XS_STRIDE];

    int t  = threadIdx.x;
    int tx = t & 15;
    int ty = t >> 4;
    int base = blockIdx.x * 64;

    int m_l = t >> 2, q_l = t & 3;

    float4 acc[4];
#pragma unroll
    for (int i = 0; i < 4; i++) acc[i] = make_float4(0.f, 0.f, 0.f, 0.f);

    const float4* xrow = (const float4*)(x + (size_t)(base + m_l) * INF);
    bool mvalid = (base + m_l) < N;

#pragma unroll
    for (int half = 0; half < 2; half++) {
        {
            const float4* wp = (const float4*)(g_wt + half * 128 * 64);
            float4* wsp = (float4*)Ws;
#pragma unroll
            for (int i = 0; i < 8; i++) wsp[t + 256 * i] = __ldg(wp + t + 256 * i);
        }
        {
            float4 v = make_float4(0.f, 0.f, 0.f, 0.f);
            if (mvalid) v = __ldg(xrow + (half * 8) * 4 + q_l);
            float* dst = xs[0];
            dst[(q_l * 4 + 0) * XS_STRIDE + m_l] = v.x;
            dst[(q_l * 4 + 1) * XS_STRIDE + m_l] = v.y;
            dst[(q_l * 4 + 2) * XS_STRIDE + m_l] = v.z;
            dst[(q_l * 4 + 3) * XS_STRIDE + m_l] = v.w;
        }
        __syncthreads();

#pragma unroll
        for (int kc = 0; kc < 8; kc++) {
            int buf = kc & 1;
            if (kc < 7) {
                float4 v = make_float4(0.f, 0.f, 0.f, 0.f);
                if (mvalid) v = __ldg(xrow + (half * 8 + kc + 1) * 4 + q_l);
                float* dst = xs[buf ^ 1];
                dst[(q_l * 4 + 0) * XS_STRIDE + m_l] = v.x;
                dst[(q_l * 4 + 1) * XS_STRIDE + m_l] = v.y;
                dst[(q_l * 4 + 2) * XS_STRIDE + m_l] = v.z;
                dst[(q_l * 4 + 3) * XS_STRIDE + m_l] = v.w;
            }
#pragma unroll
            for (int kk = 0; kk < 16; kk++) {
                float4 bv = *(const float4*)&Ws[(kc * 16 + kk) * 64 + tx * 4];
                float4 av = *(const float4*)&xs[buf][kk * XS_STRIDE + ty * 4];
                acc[0].x += av.x * bv.x; acc[0].y += av.x * bv.y;
                acc[0].z += av.x * bv.z; acc[0].w += av.x * bv.w;
                acc[1].x += av.y * bv.x; acc[1].y += av.y * bv.y;
                acc[1].z += av.y * bv.z; acc[1].w += av.y * bv.w;
                acc[2].x += av.z * bv.x; acc[2].y += av.z * bv.y;
                acc[2].z += av.z * bv.z; acc[2].w += av.z * bv.w;
                acc[3].x += av.w * bv.x; acc[3].y += av.w * bv.y;
                acc[3].z += av.w * bv.z; acc[3].w += av.w * bv.w;
            }
            __syncthreads();
        }
    }

    float4 b4  = __ldg((const float4*)b + tx);
    float4 a1v = __ldg((const float4*)a + tx);
    float4 a2v = __ldg((const float4*)(a + OUTF) + tx);

#pragma unroll
    for (int mi = 0; mi < 4; mi++) {
        int node = base + ty * 4 + mi;
        float4 h;
        h.x = acc[mi].x + b4.x; h.y = acc[mi].y + b4.y;
        h.z = acc[mi].z + b4.z; h.w = acc[mi].w + b4.w;
        if (node < N) {
            *((float4*)(g_h + (size_t)node * OUTF) + tx) = h;
            // fp16 copy for the aggregation gather
            __half2 p0 = __floats2half2_rn(h.x, h.y);
            __half2 p1 = __floats2half2_rn(h.z, h.w);
            uint2 u = make_uint2(*(unsigned*)&p0, *(unsigned*)&p1);
            *((uint2*)(g_hh + (size_t)node * OUTF) + tx) = u;
        }
        float p1 = h.x * a1v.x + h.y * a1v.y + h.z * a1v.z + h.w * a1v.w;
        float p2 = h.x * a2v.x + h.y * a2v.y + h.z * a2v.z + h.w * a2v.w;
#pragma unroll
        for (int off = 8; off; off >>= 1) {
            p1 += __shfl_xor_sync(0xffffffffu, p1, off);
            p2 += __shfl_xor_sync(0xffffffffu, p2, off);
        }
        if (tx == 0 && node < N) {
            g_s1[node] = p1;
            g_s2[node] = p2;
        }
    }
}

// ---------------------------------------------------------------------------
// Single adj pass: convert to int32 + degree histogram by src
// ---------------------------------------------------------------------------
__global__ void k_convdeg(const void* __restrict__ adj, int E) {
    int i = blockIdx.x * blockDim.x + threadIdx.x;
    if (i >= E) return;
    int s, d;
    if (g_is64) {
        const long long* a = (const long long*)adj;
        s = (int)a[i];
        d = (int)a[(size_t)i + E];
    } else {
        const int* a = (const int*)adj;
        s = a[i];
        d = a[(size_t)i + E];
    }
    g_src[i] = s;
    g_dst[i] = d;
    atomicAdd(&g_deg[s], 1);
}

// ---------------------------------------------------------------------------
// Exclusive scan of g_deg -> g_ptr
// ---------------------------------------------------------------------------
__global__ void k_scanA(int N) {
    __shared__ int sh[1024];
    int i = blockIdx.x * 1024 + threadIdx.x;
    int v = (i < N) ? g_deg[i] : 0;
    sh[threadIdx.x] = v;
    __syncthreads();
#pragma unroll
    for (int off = 1; off < 1024; off <<= 1) {
        int add = (threadIdx.x >= off) ? sh[threadIdx.x - off] : 0;
        __syncthreads();
        sh[threadIdx.x] += add;
        __syncthreads();
    }
    if (i < N) g_ptr[i] = sh[threadIdx.x] - v;
    if (threadIdx.x == 1023) g_bsum[blockIdx.x] = sh[1023];
}

__global__ void k_scanB(int nb) {
    __shared__ int sh[128];
    int t = threadIdx.x;
    int v = (t < nb) ? g_bsum[t] : 0;
    sh[t] = v;
    __syncthreads();
#pragma unroll
    for (int off = 1; off < 128; off <<= 1) {
        int add = (t >= off) ? sh[t - off] : 0;
        __syncthreads();
        sh[t] += add;
        __syncthreads();
    }
    if (t < nb) g_bsum[t] = sh[t] - v;
}

__global__ void k_scanC(int N) {
    int i = blockIdx.x * blockDim.x + threadIdx.x;
    if (i < N) {
        int p = g_ptr[i] + g_bsum[i >> 10];
        g_ptr[i] = p;
        g_cur[i] = p;
    }
}

// ---------------------------------------------------------------------------
// Fused: ex = exp(leakyrelu(s1[src]+s2[dst])), denom atomic, CSR scatter.
// ---------------------------------------------------------------------------
__global__ void k_edge12(int E) {
    int i = blockIdx.x * blockDim.x + threadIdx.x;
    if (i >= E) return;
    int s = g_src[i];
    int d = g_dst[i];
    float e = g_s1[s] + g_s2[d];
    e = e > 0.f ? e : ALPHA * e;
    float ex = __expf(e);
    atomicAdd(&g_den[d], ex);
    int pos = atomicAdd(&g_cur[s], 1);
    g_pack[pos] = make_int2(d, __float_as_int(ex));
}

// ---------------------------------------------------------------------------
// CSR aggregation with fp16 h gather: 16 lanes/node, uint2 (4 halves) per lane.
// ---------------------------------------------------------------------------
__global__ void __launch_bounds__(256) k_edge3(float* __restrict__ out, int N) {
    int t = threadIdx.x;
    int node = blockIdx.x * 16 + (t >> 4);
    int lane = t & 15;
    if (node >= N) return;
    int start = g_ptr[node];
    int deg   = g_deg[node];
    float4 acc = make_float4(0.f, 0.f, 0.f, 0.f);
    if (deg > 0) {
        int2 p = __ldg(&g_pack[start]);
        for (int j = 0; j < deg - 1; j++) {
            int2 pn = __ldg(&g_pack[start + j + 1]);
            int d = p.x;
            float att = __fdividef(__int_as_float(p.y), __ldg(&g_den[d]));
            uint2 u = __ldg((const uint2*)(g_hh + (size_t)d * OUTF) + lane);
            float2 f0 = __half22float2(*(__half2*)&u.x);
            float2 f1 = __half22float2(*(__half2*)&u.y);
            acc.x += att * f0.x; acc.y += att * f0.y;
            acc.z += att * f1.x; acc.w += att * f1.y;
            p = pn;
        }
        int d = p.x;
        float att = __fdividef(__int_as_float(p.y), __ldg(&g_den[d]));
        uint2 u = __ldg((const uint2*)(g_hh + (size_t)d * OUTF) + lane);
        float2 f0 = __half22float2(*(__half2*)&u.x);
        float2 f1 = __half22float2(*(__half2*)&u.y);
        acc.x += att * f0.x; acc.y += att * f0.y;
        acc.z += att * f1.x; acc.w += att * f1.y;
    }
    acc.x = acc.x > 0.f ? acc.x : expm1f(acc.x);
    acc.y = acc.y > 0.f ? acc.y : expm1f(acc.y);
    acc.z = acc.z > 0.f ? acc.z : expm1f(acc.z);
    acc.w = acc.w > 0.f ? acc.w : expm1f(acc.w);
    *((float4*)(out + (size_t)node * OUTF) + lane) = acc;
}

extern "C" void kernel_launch(void* const* d_in, const int* in_sizes, int n_in,
                              void* d_out, int out_size)
{
    const void*  adj = d_in[0];
    const float* x   = (const float*)d_in[1];
    const float* W   = (const float*)d_in[2];
    const float* b   = (const float*)d_in[3];
    const float* a   = (const float*)d_in[4];
    float* out = (float*)d_out;

    int E = in_sizes[0] / 2;
    int N = in_sizes[1] / INF;
    int nScanBlocks = (N + 1023) / 1024;

    k_detect<<<1, 256>>>((const int*)adj, E);
    k_wt<<<(INF * OUTF + 255) / 256, 256>>>(W);
    k_init<<<(N + 255) / 256, 256>>>(N);
    k_gemm<<<(N + 63) / 64, 256>>>(x, b, a, N);   // slot 4: profiled control
    k_convdeg<<<(E + 255) / 256, 256>>>(adj, E);
    k_scanA<<<nScanBlocks, 1024>>>(N);
    k_scanB<<<1, 128>>>(nScanBlocks);
    k_scanC<<<(N + 255) / 256, 256>>>(N);
    k_edge12<<<(E + 255) / 256, 256>>>(E);
    k_edge3<<<(N + 15) / 16, 256>>>(out, N);
}

// round 7
// speedup vs baseline: 1.4767x; 1.1735x over previous
#include <cuda_runtime.h>
#include <cuda_fp16.h>
#include <cuda_bf16.h>
#include <cstdint>

#define MAXN 100000
#define MAXE 3200000
#define INF  256
#define OUTF 64
#define ALPHA 0.2f

// Static scratch
__device__ __half g_hh[(size_t)MAXN * OUTF];  // 12.8 MB (fp16 h for gather)
__device__ float  g_s1[MAXN];
__device__ float  g_s2[MAXN];
__device__ float  g_den[MAXN];
__device__ int    g_deg[MAXN];
__device__ int    g_ptr[MAXN];
__device__ int    g_cur[MAXN];
__device__ int    g_bsum[128];
__device__ int2   g_pack[MAXE];               // (dst, exp(e)) grouped by src
__device__ __nv_bfloat16 g_whi[INF * OUTF];   // W hi, layout [o][k]
__device__ __nv_bfloat16 g_wlo[INF * OUTF];   // W lo, layout [o][k]
__device__ int    g_is64;

// ---------------------------------------------------------------------------
__global__ void k_detect(const int* __restrict__ adj32, int E) {
    __shared__ int sh[256];
    int t = threadIdx.x;
    int acc = 0;
#pragma unroll
    for (int j = 0; j < 4; j++) {
        int idx = 2 * (t * 4 + j) + 1;
        if (idx < 2 * E) acc |= adj32[idx];
    }
    sh[t] = acc;
    __syncthreads();
    for (int s = 128; s; s >>= 1) {
        if (t < s) sh[t] |= sh[t + s];
        __syncthreads();
    }
    if (t == 0) g_is64 = (sh[0] == 0) ? 1 : 0;
}

// Split W into bf16 hi/lo, keeping [o][k] layout
__global__ void k_wt(const float* __restrict__ W) {
    int i = blockIdx.x * blockDim.x + threadIdx.x;
    if (i < INF * OUTF) {
        float w = W[i];
        __nv_bfloat16 hi = __float2bfloat16_rn(w);
        __nv_bfloat16 lo = __float2bfloat16_rn(w - __bfloat162float(hi));
        g_whi[i] = hi;
        g_wlo[i] = lo;
    }
}

__global__ void k_init(int N) {
    int i = blockIdx.x * blockDim.x + threadIdx.x;
    if (i < N) { g_den[i] = 0.0f; g_deg[i] = 0; }
}

// ---------------------------------------------------------------------------
// Tensor-core GEMM: h = x @ W^T + b via 3-term bf16 split (~fp32 precision).
// Block 256 thr = 8 warps; tile M=128 (16/warp) x N=64. K in 16 steps of 16.
// mma.sync.m16n8k16 row.col: A = x slab [128][16] bf16, B = W slab [64][16].
// ---------------------------------------------------------------------------
#define XPITCH 18   // halves per xs row (bank-spread)
#define WPITCH 24   // halves per ws row (16B-aligned staging, conflict-free LDS)

__device__ __forceinline__ void mma_bf16(float* d, const uint32_t* a,
                                         uint32_t b0, uint32_t b1) {
    asm volatile(
        "mma.sync.aligned.m16n8k16.row.col.f32.bf16.bf16.f32 "
        "{%0,%1,%2,%3}, {%4,%5,%6,%7}, {%8,%9}, {%0,%1,%2,%3};"
        : "+f"(d[0]), "+f"(d[1]), "+f"(d[2]), "+f"(d[3])
        : "r"(a[0]), "r"(a[1]), "r"(a[2]), "r"(a[3]), "r"(b0), "r"(b1));
}

__global__ void __launch_bounds__(256) k_gemm(
    const float* __restrict__ x, const float* __restrict__ b,
    const float* __restrict__ a, int N)
{
    __shared__ __nv_bfloat16 xs_hi[2][128 * XPITCH];
    __shared__ __nv_bfloat16 xs_lo[2][128 * XPITCH];
    __shared__ __nv_bfloat16 ws_hi[2][64 * WPITCH];
    __shared__ __nv_bfloat16 ws_lo[2][64 * WPITCH];

    int t    = threadIdx.x;
    int warp = t >> 5;
    int lane = t & 31;
    int g    = lane >> 2;   // group id (row within frag)
    int tig  = lane & 3;    // thread in group (col pairs)
    int base = blockIdx.x * 128;
    int m0   = warp * 16;   // this warp's node offset within tile

    float d[8][4];
#pragma unroll
    for (int n = 0; n < 8; n++)
#pragma unroll
        for (int i = 0; i < 4; i++) d[n][i] = 0.f;

    // --- staging lambda-ish macros (inline) ---
    // x slab: 128 nodes x 16 k fp32 -> hi/lo bf16. 512 float4; 2 per thread.
    // W slab: threads t<128 stage hi, t>=128 stage lo (uint4 copies).

#define STAGE(BUF, KS)                                                        \
    {                                                                         \
        int ks_ = (KS);                                                       \
        _Pragma("unroll")                                                     \
        for (int r = 0; r < 2; r++) {                                         \
            int idx = t + 256 * r;                                            \
            int row = idx >> 2, q = idx & 3;                                  \
            int node = base + row;                                            \
            float4 v = make_float4(0.f, 0.f, 0.f, 0.f);                       \
            if (node < N)                                                     \
                v = __ldg((const float4*)(x + (size_t)node * INF) + ks_ * 4 + q); \
            __nv_bfloat16 bx = __float2bfloat16_rn(v.x);                      \
            __nv_bfloat16 by = __float2bfloat16_rn(v.y);                      \
            __nv_bfloat16 bz = __float2bfloat16_rn(v.z);                      \
            __nv_bfloat16 bw = __float2bfloat16_rn(v.w);                      \
            __nv_bfloat16 lx = __float2bfloat16_rn(v.x - __bfloat162float(bx)); \
            __nv_bfloat16 ly = __float2bfloat16_rn(v.y - __bfloat162float(by)); \
            __nv_bfloat16 lz = __float2bfloat16_rn(v.z - __bfloat162float(bz)); \
            __nv_bfloat16 lw = __float2bfloat16_rn(v.w - __bfloat162float(bw)); \
            int o0 = row * XPITCH + q * 4;                                    \
            *(__nv_bfloat162*)&xs_hi[BUF][o0]     = __halves2bfloat162(bx, by); \
            *(__nv_bfloat162*)&xs_hi[BUF][o0 + 2] = __halves2bfloat162(bz, bw); \
            *(__nv_bfloat162*)&xs_lo[BUF][o0]     = __halves2bfloat162(lx, ly); \
            *(__nv_bfloat162*)&xs_lo[BUF][o0 + 2] = __halves2bfloat162(lz, lw); \
        }                                                                     \
        {                                                                     \
            int tt = t & 127;                                                 \
            int o = tt >> 1, half = tt & 1;                                   \
            const __nv_bfloat16* srcb = (t < 128) ? g_whi : g_wlo;            \
            __nv_bfloat16* dstb = (t < 128) ? ws_hi[BUF] : ws_lo[BUF];        \
            uint4 wv = *(const uint4*)(srcb + o * INF + ks_ * 16 + half * 8); \
            *(uint4*)(dstb + o * WPITCH + half * 8) = wv;                     \
        }                                                                     \
    }

    STAGE(0, 0);
    __syncthreads();

    int buf = 0;
#pragma unroll
    for (int ks = 0; ks < 16; ks++) {
        if (ks < 15) STAGE(buf ^ 1, ks + 1);

        // A fragments for this warp (rows m0+g, m0+g+8; k pairs 2tig, 2tig+8)
        uint32_t a_hi[4], a_lo[4];
        {
            int r0 = (m0 + g) * XPITCH + 2 * tig;
            int r1 = (m0 + g + 8) * XPITCH + 2 * tig;
            a_hi[0] = *(const uint32_t*)&xs_hi[buf][r0];
            a_hi[1] = *(const uint32_t*)&xs_hi[buf][r1];
            a_hi[2] = *(const uint32_t*)&xs_hi[buf][r0 + 8];
            a_hi[3] = *(const uint32_t*)&xs_hi[buf][r1 + 8];
            a_lo[0] = *(const uint32_t*)&xs_lo[buf][r0];
            a_lo[1] = *(const uint32_t*)&xs_lo[buf][r1];
            a_lo[2] = *(const uint32_t*)&xs_lo[buf][r0 + 8];
            a_lo[3] = *(const uint32_t*)&xs_lo[buf][r1 + 8];
        }
#pragma unroll
        for (int n = 0; n < 8; n++) {
            int wb = (n * 8 + g) * WPITCH + 2 * tig;
            uint32_t bh0 = *(const uint32_t*)&ws_hi[buf][wb];
            uint32_t bh1 = *(const uint32_t*)&ws_hi[buf][wb + 8];
            uint32_t bl0 = *(const uint32_t*)&ws_lo[buf][wb];
            uint32_t bl1 = *(const uint32_t*)&ws_lo[buf][wb + 8];
            mma_bf16(d[n], a_hi, bh0, bh1);
            mma_bf16(d[n], a_hi, bl0, bl1);
            mma_bf16(d[n], a_lo, bh0, bh1);
        }
        __syncthreads();
        buf ^= 1;
    }

    // Epilogue: bias, fp16 h store, fused s1/s2
    int node0 = base + m0 + g;
    int node1 = node0 + 8;
    float p1a = 0.f, p2a = 0.f, p1b = 0.f, p2b = 0.f;
#pragma unroll
    for (int n = 0; n < 8; n++) {
        int o0 = n * 8 + tig * 2;
        float bb0 = __ldg(b + o0), bb1 = __ldg(b + o0 + 1);
        float h0 = d[n][0] + bb0, h1 = d[n][1] + bb1;   // row g
        float h2 = d[n][2] + bb0, h3 = d[n][3] + bb1;   // row g+8
        if (node0 < N)
            *(__half2*)(g_hh + (size_t)node0 * OUTF + o0) = __floats2half2_rn(h0, h1);
        if (node1 < N)
            *(__half2*)(g_hh + (size_t)node1 * OUTF + o0) = __floats2half2_rn(h2, h3);
        float a10 = __ldg(a + o0), a11 = __ldg(a + o0 + 1);
        float a20 = __ldg(a + OUTF + o0), a21 = __ldg(a + OUTF + o0 + 1);
        p1a += h0 * a10 + h1 * a11;
        p2a += h0 * a20 + h1 * a21;
        p1b += h2 * a10 + h3 * a11;
        p2b += h2 * a20 + h3 * a21;
    }
#pragma unroll
    for (int off = 1; off <= 2; off <<= 1) {
        p1a += __shfl_xor_sync(0xffffffffu, p1a, off);
        p2a += __shfl_xor_sync(0xffffffffu, p2a, off);
        p1b += __shfl_xor_sync(0xffffffffu, p1b, off);
        p2b += __shfl_xor_sync(0xffffffffu, p2b, off);
    }
    if (tig == 0) {
        if (node0 < N) { g_s1[node0] = p1a; g_s2[node0] = p2a; }
        if (node1 < N) { g_s1[node1] = p1b; g_s2[node1] = p2b; }
    }
}

// ---------------------------------------------------------------------------
// Degree histogram over src (reads adj directly)
// ---------------------------------------------------------------------------
__global__ void k_hist(const void* __restrict__ adj, int E) {
    int i = blockIdx.x * blockDim.x + threadIdx.x;
    if (i >= E) return;
    int s = g_is64 ? (int)((const long long*)adj)[i] : ((const int*)adj)[i];
    atomicAdd(&g_deg[s], 1);
}

// ---------------------------------------------------------------------------
// Exclusive scan of g_deg -> g_ptr
// ---------------------------------------------------------------------------
__global__ void k_scanA(int N) {
    __shared__ int sh[1024];
    int i = blockIdx.x * 1024 + threadIdx.x;
    int v = (i < N) ? g_deg[i] : 0;
    sh[threadIdx.x] = v;
    __syncthreads();
#pragma unroll
    for (int off = 1; off < 1024; off <<= 1) {
        int add = (threadIdx.x >= off) ? sh[threadIdx.x - off] : 0;
        __syncthreads();
        sh[threadIdx.x] += add;
        __syncthreads();
    }
    if (i < N) g_ptr[i] = sh[threadIdx.x] - v;
    if (threadIdx.x == 1023) g_bsum[blockIdx.x] = sh[1023];
}

__global__ void k_scanB(int nb) {
    __shared__ int sh[128];
    int t = threadIdx.x;
    int v = (t < nb) ? g_bsum[t] : 0;
    sh[t] = v;
    __syncthreads();
#pragma unroll
    for (int off = 1; off < 128; off <<= 1) {
        int add = (t >= off) ? sh[t - off] : 0;
        __syncthreads();
        sh[t] += add;
        __syncthreads();
    }
    if (t < nb) g_bsum[t] = sh[t] - v;
}

__global__ void k_scanC(int N) {
    int i = blockIdx.x * blockDim.x + threadIdx.x;
    if (i < N) {
        int p = g_ptr[i] + g_bsum[i >> 10];
        g_ptr[i] = p;
        g_cur[i] = p;
    }
}

// ---------------------------------------------------------------------------
// Fused: read adj, ex = exp(leakyrelu(s1[src]+s2[dst])), denom, CSR scatter.
// ---------------------------------------------------------------------------
__global__ void k_edge12(const void* __restrict__ adj, int E) {
    int i = blockIdx.x * blockDim.x + threadIdx.x;
    if (i >= E) return;
    int s, d;
    if (g_is64) {
        const long long* a = (const long long*)adj;
        s = (int)a[i];
        d = (int)a[(size_t)i + E];
    } else {
        const int* a = (const int*)adj;
        s = a[i];
        d = a[(size_t)i + E];
    }
    float e = g_s1[s] + g_s2[d];
    e = e > 0.f ? e : ALPHA * e;
    float ex = __expf(e);
    atomicAdd(&g_den[d], ex);
    int pos = atomicAdd(&g_cur[s], 1);
    g_pack[pos] = make_int2(d, __float_as_int(ex));
}

// ---------------------------------------------------------------------------
// CSR aggregation with fp16 h gather: 16 lanes/node
// ---------------------------------------------------------------------------
__global__ void __launch_bounds__(256) k_edge3(float* __restrict__ out, int N) {
    int t = threadIdx.x;
    int node = blockIdx.x * 16 + (t >> 4);
    int lane = t & 15;
    if (node >= N) return;
    int start = g_ptr[node];
    int deg   = g_deg[node];
    float4 acc = make_float4(0.f, 0.f, 0.f, 0.f);
    if (deg > 0) {
        int2 p = __ldg(&g_pack[start]);
        for (int j = 0; j < deg - 1; j++) {
            int2 pn = __ldg(&g_pack[start + j + 1]);
            int d = p.x;
            float att = __fdividef(__int_as_float(p.y), __ldg(&g_den[d]));
            uint2 u = __ldg((const uint2*)(g_hh + (size_t)d * OUTF) + lane);
            float2 f0 = __half22float2(*(__half2*)&u.x);
            float2 f1 = __half22float2(*(__half2*)&u.y);
            acc.x += att * f0.x; acc.y += att * f0.y;
            acc.z += att * f1.x; acc.w += att * f1.y;
            p = pn;
        }
        int d = p.x;
        float att = __fdividef(__int_as_float(p.y), __ldg(&g_den[d]));
        uint2 u = __ldg((const uint2*)(g_hh + (size_t)d * OUTF) + lane);
        float2 f0 = __half22float2(*(__half2*)&u.x);
        float2 f1 = __half22float2(*(__half2*)&u.y);
        acc.x += att * f0.x; acc.y += att * f0.y;
        acc.z += att * f1.x; acc.w += att * f1.y;
    }
    acc.x = acc.x > 0.f ? acc.x : expm1f(acc.x);
    acc.y = acc.y > 0.f ? acc.y : expm1f(acc.y);
    acc.z = acc.z > 0.f ? acc.z : expm1f(acc.z);
    acc.w = acc.w > 0.f ? acc.w : expm1f(acc.w);
    *((float4*)(out + (size_t)node * OUTF) + lane) = acc;
}

extern "C" void kernel_launch(void* const* d_in, const int* in_sizes, int n_in,
                              void* d_out, int out_size)
{
    const void*  adj = d_in[0];
    const float* x   = (const float*)d_in[1];
    const float* W   = (const float*)d_in[2];
    const float* b   = (const float*)d_in[3];
    const float* a   = (const float*)d_in[4];
    float* out = (float*)d_out;

    int E = in_sizes[0] / 2;
    int N = in_sizes[1] / INF;
    int nScanBlocks = (N + 1023) / 1024;

    k_detect<<<1, 256>>>((const int*)adj, E);
    k_wt<<<(INF * OUTF + 255) / 256, 256>>>(W);
    k_init<<<(N + 255) / 256, 256>>>(N);
    k_gemm<<<(N + 127) / 128, 256>>>(x, b, a, N);   // slot 4: profiled
    k_hist<<<(E + 255) / 256, 256>>>(adj, E);
    k_scanA<<<nScanBlocks, 1024>>>(N);
    k_scanB<<<1, 128>>>(nScanBlocks);
    k_scanC<<<(N + 255) / 256, 256>>>(N);
    k_edge12<<<(E + 255) / 256, 256>>>(adj, E);
    k_edge3<<<(N + 15) / 16, 256>>>(out, N);
}

// round 8
// speedup vs baseline: 1.5588x; 1.0556x over previous
#include <cuda_runtime.h>
#include <cuda_fp16.h>
#include <cuda_bf16.h>
#include <cstdint>

#define MAXN 100000
#define MAXE 3200000
#define INF  256
#define OUTF 64
#define ALPHA 0.2f

// Static scratch
__device__ __half g_hh[(size_t)MAXN * OUTF];  // 12.8 MB (fp16 h for gather)
__device__ float  g_s1[MAXN];
__device__ float  g_s2[MAXN];
__device__ float  g_den[MAXN];
__device__ int    g_deg[MAXN];
__device__ int    g_ptr[MAXN];
__device__ int    g_cur[MAXN];
__device__ int    g_bsum[128];
__device__ int2   g_pack[MAXE];               // (dst, exp(e)) grouped by src
__device__ uint4  g_wp[16 * 64 * 4];          // W fragment-packed: (ks,o,tig) -> {bh0,bh1,bl0,bl1}
__device__ int    g_is64;

// ---------------------------------------------------------------------------
__global__ void k_detect(const int* __restrict__ adj32, int E) {
    __shared__ int sh[256];
    int t = threadIdx.x;
    int acc = 0;
#pragma unroll
    for (int j = 0; j < 4; j++) {
        int idx = 2 * (t * 4 + j) + 1;
        if (idx < 2 * E) acc |= adj32[idx];
    }
    sh[t] = acc;
    __syncthreads();
    for (int s = 128; s; s >>= 1) {
        if (t < s) sh[t] |= sh[t + s];
        __syncthreads();
    }
    if (t == 0) g_is64 = (sh[0] == 0) ? 1 : 0;
}

// Pack W into mma-fragment order with bf16 hi/lo split.
// Entry (ks, o, tig): .x = hi(k0,k0+1)  .y = hi(k0+8,k0+9)
//                     .z = lo(k0,k0+1)  .w = lo(k0+8,k0+9),  k0 = ks*16+2*tig
__global__ void k_wt(const float* __restrict__ W) {
    int i = blockIdx.x * blockDim.x + threadIdx.x;
    if (i >= 16 * 64 * 4) return;
    int tig = i & 3;
    int o   = (i >> 2) & 63;
    int ks  = i >> 8;
    int k0  = ks * 16 + 2 * tig;
    float w0 = W[o * INF + k0],     w1 = W[o * INF + k0 + 1];
    float w8 = W[o * INF + k0 + 8], w9 = W[o * INF + k0 + 9];
    __nv_bfloat162 h01 = __floats2bfloat162_rn(w0, w1);
    __nv_bfloat162 h89 = __floats2bfloat162_rn(w8, w9);
    __nv_bfloat162 l01 = __floats2bfloat162_rn(w0 - __bfloat162float(h01.x),
                                               w1 - __bfloat162float(h01.y));
    __nv_bfloat162 l89 = __floats2bfloat162_rn(w8 - __bfloat162float(h89.x),
                                               w9 - __bfloat162float(h89.y));
    uint4 u;
    u.x = *(unsigned*)&h01; u.y = *(unsigned*)&h89;
    u.z = *(unsigned*)&l01; u.w = *(unsigned*)&l89;
    g_wp[i] = u;
}

__global__ void k_init(int N) {
    int i = blockIdx.x * blockDim.x + threadIdx.x;
    if (i < N) { g_den[i] = 0.0f; g_deg[i] = 0; }
}

// ---------------------------------------------------------------------------
// Tensor-core GEMM, zero-smem: A fragments straight from gmem (fp32->bf16
// hi/lo in regs), W fragments via one LDG.128 per (n, ks) from L1-resident
// packed layout. 3-term split ~= fp32 precision.
// Block 256 = 8 warps, tile M=128 (16 rows/warp) x N=64.
// ---------------------------------------------------------------------------
__device__ __forceinline__ void mma_bf16(float* d, const uint32_t* a,
                                         uint32_t b0, uint32_t b1) {
    asm volatile(
        "mma.sync.aligned.m16n8k16.row.col.f32.bf16.bf16.f32 "
        "{%0,%1,%2,%3}, {%4,%5,%6,%7}, {%8,%9}, {%0,%1,%2,%3};"
        : "+f"(d[0]), "+f"(d[1]), "+f"(d[2]), "+f"(d[3])
        : "r"(a[0]), "r"(a[1]), "r"(a[2]), "r"(a[3]), "r"(b0), "r"(b1));
}

__device__ __forceinline__ uint32_t pack_hi(float2 v, float2* res) {
    __nv_bfloat162 h = __floats2bfloat162_rn(v.x, v.y);
    res->x = v.x - __bfloat162float(h.x);
    res->y = v.y - __bfloat162float(h.y);
    return *(unsigned*)&h;
}
__device__ __forceinline__ uint32_t pack_lo(float2 r) {
    __nv_bfloat162 l = __floats2bfloat162_rn(r.x, r.y);
    return *(unsigned*)&l;
}

__global__ void __launch_bounds__(256) k_gemm(
    const float* __restrict__ x, const float* __restrict__ b,
    const float* __restrict__ a, int N)
{
    int t    = threadIdx.x;
    int warp = t >> 5;
    int lane = t & 31;
    int g    = lane >> 2;
    int tig  = lane & 3;
    int base = blockIdx.x * 128;
    int m0   = warp * 16;

    int node0 = base + m0 + g;
    int node1 = node0 + 8;
    bool v0 = node0 < N, v1 = node1 < N;
    const float2* x0 = (const float2*)(x + (size_t)node0 * INF);
    const float2* x1 = (const float2*)(x + (size_t)node1 * INF);

    float d[8][4];
#pragma unroll
    for (int n = 0; n < 8; n++)
#pragma unroll
        for (int i = 0; i < 4; i++) d[n][i] = 0.f;

    const float2 z2 = make_float2(0.f, 0.f);

#pragma unroll 4
    for (int ks = 0; ks < 16; ks++) {
        // A fragments: rows g/g+8, k = ks*16 + 2tig (+8)
        float2 w00 = v0 ? __ldg(x0 + ks * 8 + tig)     : z2;  // row0, k
        float2 w01 = v0 ? __ldg(x0 + ks * 8 + tig + 4) : z2;  // row0, k+8
        float2 w10 = v1 ? __ldg(x1 + ks * 8 + tig)     : z2;  // row1, k
        float2 w11 = v1 ? __ldg(x1 + ks * 8 + tig + 4) : z2;  // row1, k+8

        uint32_t a_hi[4], a_lo[4];
        float2 r;
        a_hi[0] = pack_hi(w00, &r); a_lo[0] = pack_lo(r);
        a_hi[1] = pack_hi(w10, &r); a_lo[1] = pack_lo(r);
        a_hi[2] = pack_hi(w01, &r); a_lo[2] = pack_lo(r);
        a_hi[3] = pack_hi(w11, &r); a_lo[3] = pack_lo(r);

        const uint4* wrow = g_wp + (ks * 64 + g) * 4 + tig;
#pragma unroll
        for (int n = 0; n < 8; n++) {
            uint4 wv = __ldg(wrow + n * 32);   // (ks, o = n*8+g, tig)
            mma_bf16(d[n], a_hi, wv.x, wv.y);
            mma_bf16(d[n], a_hi, wv.z, wv.w);
            mma_bf16(d[n], a_lo, wv.x, wv.y);
        }
    }

    // Epilogue: bias, fp16 h store, fused s1/s2
    float p1a = 0.f, p2a = 0.f, p1b = 0.f, p2b = 0.f;
#pragma unroll
    for (int n = 0; n < 8; n++) {
        int o0 = n * 8 + tig * 2;
        float bb0 = __ldg(b + o0), bb1 = __ldg(b + o0 + 1);
        float h0 = d[n][0] + bb0, h1 = d[n][1] + bb1;   // row g
        float h2 = d[n][2] + bb0, h3 = d[n][3] + bb1;   // row g+8
        if (v0)
            *(__half2*)(g_hh + (size_t)node0 * OUTF + o0) = __floats2half2_rn(h0, h1);
        if (v1)
            *(__half2*)(g_hh + (size_t)node1 * OUTF + o0) = __floats2half2_rn(h2, h3);
        float a10 = __ldg(a + o0), a11 = __ldg(a + o0 + 1);
        float a20 = __ldg(a + OUTF + o0), a21 = __ldg(a + OUTF + o0 + 1);
        p1a += h0 * a10 + h1 * a11;
        p2a += h0 * a20 + h1 * a21;
        p1b += h2 * a10 + h3 * a11;
        p2b += h2 * a20 + h3 * a21;
    }
#pragma unroll
    for (int off = 1; off <= 2; off <<= 1) {
        p1a += __shfl_xor_sync(0xffffffffu, p1a, off);
        p2a += __shfl_xor_sync(0xffffffffu, p2a, off);
        p1b += __shfl_xor_sync(0xffffffffu, p1b, off);
        p2b += __shfl_xor_sync(0xffffffffu, p2b, off);
    }
    if (tig == 0) {
        if (v0) { g_s1[node0] = p1a; g_s2[node0] = p2a; }
        if (v1) { g_s1[node1] = p1b; g_s2[node1] = p2b; }
    }
}

// ---------------------------------------------------------------------------
// Degree histogram over src (low 32-bit word only when int64)
// ---------------------------------------------------------------------------
__global__ void k_hist(const void* __restrict__ adj, int E) {
    int i = blockIdx.x * blockDim.x + threadIdx.x;
    if (i >= E) return;
    int s = g_is64 ? ((const int*)adj)[2 * (size_t)i] : ((const int*)adj)[i];
    atomicAdd(&g_deg[s], 1);
}

// ---------------------------------------------------------------------------
// Exclusive scan of g_deg -> g_ptr
// ---------------------------------------------------------------------------
__global__ void k_scanA(int N) {
    __shared__ int sh[1024];
    int i = blockIdx.x * 1024 + threadIdx.x;
    int v = (i < N) ? g_deg[i] : 0;
    sh[threadIdx.x] = v;
    __syncthreads();
#pragma unroll
    for (int off = 1; off < 1024; off <<= 1) {
        int add = (threadIdx.x >= off) ? sh[threadIdx.x - off] : 0;
        __syncthreads();
        sh[threadIdx.x] += add;
        __syncthreads();
    }
    if (i < N) g_ptr[i] = sh[threadIdx.x] - v;
    if (threadIdx.x == 1023) g_bsum[blockIdx.x] = sh[1023];
}

__global__ void k_scanB(int nb) {
    __shared__ int sh[128];
    int t = threadIdx.x;
    int v = (t < nb) ? g_bsum[t] : 0;
    sh[t] = v;
    __syncthreads();
#pragma unroll
    for (int off = 1; off < 128; off <<= 1) {
        int add = (t >= off) ? sh[t - off] : 0;
        __syncthreads();
        sh[t] += add;
        __syncthreads();
    }
    if (t < nb) g_bsum[t] = sh[t] - v;
}

__global__ void k_scanC(int N) {
    int i = blockIdx.x * blockDim.x + threadIdx.x;
    if (i < N) {
        int p = g_ptr[i] + g_bsum[i >> 10];
        g_ptr[i] = p;
        g_cur[i] = p;
    }
}

// ---------------------------------------------------------------------------
// Fused: read adj, ex = exp(leakyrelu(s1[src]+s2[dst])), denom, CSR scatter.
// ---------------------------------------------------------------------------
__global__ void k_edge12(const void* __restrict__ adj, int E) {
    int i = blockIdx.x * blockDim.x + threadIdx.x;
    if (i >= E) return;
    int s, d;
    if (g_is64) {
        const int* a = (const int*)adj;
        s = a[2 * (size_t)i];
        d = a[2 * ((size_t)i + E)];
    } else {
        const int* a = (const int*)adj;
        s = a[i];
        d = a[(size_t)i + E];
    }
    float e = g_s1[s] + g_s2[d];
    e = e > 0.f ? e : ALPHA * e;
    float ex = __expf(e);
    atomicAdd(&g_den[d], ex);
    int pos = atomicAdd(&g_cur[s], 1);
    g_pack[pos] = make_int2(d, __float_as_int(ex));
}

// ---------------------------------------------------------------------------
// CSR aggregation with fp16 h gather: 16 lanes/node
// ---------------------------------------------------------------------------
__global__ void __launch_bounds__(256) k_edge3(float* __restrict__ out, int N) {
    int t = threadIdx.x;
    int node = blockIdx.x * 16 + (t >> 4);
    int lane = t & 15;
    if (node >= N) return;
    int start = g_ptr[node];
    int deg   = g_deg[node];
    float4 acc = make_float4(0.f, 0.f, 0.f, 0.f);
    if (deg > 0) {
        int2 p = __ldg(&g_pack[start]);
        for (int j = 0; j < deg - 1; j++) {
            int2 pn = __ldg(&g_pack[start + j + 1]);
            int d = p.x;
            float att = __fdividef(__int_as_float(p.y), __ldg(&g_den[d]));
            uint2 u = __ldg((const uint2*)(g_hh + (size_t)d * OUTF) + lane);
            float2 f0 = __half22float2(*(__half2*)&u.x);
            float2 f1 = __half22float2(*(__half2*)&u.y);
            acc.x += att * f0.x; acc.y += att * f0.y;
            acc.z += att * f1.x; acc.w += att * f1.y;
            p = pn;
        }
        int d = p.x;
        float att = __fdividef(__int_as_float(p.y), __ldg(&g_den[d]));
        uint2 u = __ldg((const uint2*)(g_hh + (size_t)d * OUTF) + lane);
        float2 f0 = __half22float2(*(__half2*)&u.x);
        float2 f1 = __half22float2(*(__half2*)&u.y);
        acc.x += att * f0.x; acc.y += att * f0.y;
        acc.z += att * f1.x; acc.w += att * f1.y;
    }
    acc.x = acc.x > 0.f ? acc.x : expm1f(acc.x);
    acc.y = acc.y > 0.f ? acc.y : expm1f(acc.y);
    acc.z = acc.z > 0.f ? acc.z : expm1f(acc.z);
    acc.w = acc.w > 0.f ? acc.w : expm1f(acc.w);
    *((float4*)(out + (size_t)node * OUTF) + lane) = acc;
}

extern "C" void kernel_launch(void* const* d_in, const int* in_sizes, int n_in,
                              void* d_out, int out_size)
{
    const void*  adj = d_in[0];
    const float* x   = (const float*)d_in[1];
    const float* W   = (const float*)d_in[2];
    const float* b   = (const float*)d_in[3];
    const float* a   = (const float*)d_in[4];
    float* out = (float*)d_out;

    int E = in_sizes[0] / 2;
    int N = in_sizes[1] / INF;
    int nScanBlocks = (N + 1023) / 1024;

    k_detect<<<1, 256>>>((const int*)adj, E);
    k_wt<<<16, 256>>>(W);
    k_init<<<(N + 255) / 256, 256>>>(N);
    k_gemm<<<(N + 127) / 128, 256>>>(x, b, a, N);   // slot 4: profiled
    k_hist<<<(E + 255) / 256, 256>>>(adj, E);
    k_scanA<<<nScanBlocks, 1024>>>(N);
    k_scanB<<<1, 128>>>(nScanBlocks);
    k_scanC<<<(N + 255) / 256, 256>>>(N);
    k_edge12<<<(E + 255) / 256, 256>>>(adj, E);
    k_edge3<<<(N + 15) / 16, 256>>>(out, N);
}